// round 4
// baseline (speedup 1.0000x reference)
#include <cuda_runtime.h>

// Double-pendulum Hamiltonian dynamics, closed form (M1=M2=L1=L2=1, G=9.81).
// State (th1, th2, p1, p2) -> (dq1, dq2, dp1, dp2).
//
// c = cos(th1-th2), s = sin(th1-th2), D = 2 - c^2
// dq1 = (p1 - c p2)/D ; dq2 = (2 p2 - c p1)/D
// N = p1^2 - 2 c p1 p2 + 2 p2^2 ; dK/dc = (c N - D p1 p2)/D^2
// dp1 =  s dK/dc - 2 G sin(th1) ; dp2 = -s dK/dc - G sin(th2)
//
// R4: 4 states/thread via 2x 256-bit loads (front-batched), exact grid
// (no bounds check), and sincos(th1)/sincos(th2) + angle-subtraction
// identity (saves one MUFU-class op per state; FMA pipe has headroom).

#define GCONST 9.81f

__device__ __forceinline__ float4 dyn(float th1, float th2, float p1, float p2) {
    float s1, c1, s2, c2;
    __sincosf(th1, &s1, &c1);
    __sincosf(th2, &s2, &c2);

    // sin/cos(th1 - th2) via identities (FMA pipe instead of a 3rd MUFU group)
    float c = fmaf(c1, c2, s1 * s2);
    float s = fmaf(s1, c2, -c1 * s2);

    float D    = 2.0f - c * c;
    float invD = __frcp_rn(D);

    float dq1 = (p1 - c * p2) * invD;
    float dq2 = (2.0f * p2 - c * p1) * invD;

    float p1p2 = p1 * p2;
    float N    = p1 * p1 - 2.0f * c * p1p2 + 2.0f * p2 * p2;
    float dKdc = (c * N - D * p1p2) * invD * invD;

    float sd  = s * dKdc;
    float dp1 =  sd - 2.0f * GCONST * s1;
    float dp2 = -sd -        GCONST * s2;

    return make_float4(dq1, dq2, dp1, dp2);
}

__global__ void __launch_bounds__(256)
pendelum2dof_kernel(const float* __restrict__ y,
                    float* __restrict__ out) {
    // One thread = 4 states = 64 bytes. Grid is exact (B = 262144 = 256*256*4).
    int i = blockIdx.x * blockDim.x + threadIdx.x;
    const float* src = y + (size_t)i * 16;
    float* dst = out + (size_t)i * 16;

    // Front-batch both 256-bit loads (independent -> MLP=2).
    float a0, a1, a2, a3, a4, a5, a6, a7;
    float b0, b1, b2, b3, b4, b5, b6, b7;
    asm volatile("ld.global.v8.f32 {%0,%1,%2,%3,%4,%5,%6,%7}, [%8];"
                 : "=f"(a0), "=f"(a1), "=f"(a2), "=f"(a3),
                   "=f"(a4), "=f"(a5), "=f"(a6), "=f"(a7)
                 : "l"(src));
    asm volatile("ld.global.v8.f32 {%0,%1,%2,%3,%4,%5,%6,%7}, [%8];"
                 : "=f"(b0), "=f"(b1), "=f"(b2), "=f"(b3),
                   "=f"(b4), "=f"(b5), "=f"(b6), "=f"(b7)
                 : "l"(src + 8));

    float4 r0 = dyn(a0, a1, a2, a3);
    float4 r1 = dyn(a4, a5, a6, a7);
    float4 r2 = dyn(b0, b1, b2, b3);
    float4 r3 = dyn(b4, b5, b6, b7);

    asm volatile("st.global.v8.f32 [%0], {%1,%2,%3,%4,%5,%6,%7,%8};"
                 :
                 : "l"(dst),
                   "f"(r0.x), "f"(r0.y), "f"(r0.z), "f"(r0.w),
                   "f"(r1.x), "f"(r1.y), "f"(r1.z), "f"(r1.w)
                 : "memory");
    asm volatile("st.global.v8.f32 [%0], {%1,%2,%3,%4,%5,%6,%7,%8};"
                 :
                 : "l"(dst + 8),
                   "f"(r2.x), "f"(r2.y), "f"(r2.z), "f"(r2.w),
                   "f"(r3.x), "f"(r3.y), "f"(r3.z), "f"(r3.w)
                 : "memory");
}

extern "C" void kernel_launch(void* const* d_in, const int* in_sizes, int n_in,
                              void* d_out, int out_size) {
    // d_in[0] = t (unused), d_in[1] = y (B*4 floats), B = 262144
    const float* y = (const float*)d_in[1];
    float* out = (float*)d_out;
    int nstates = in_sizes[1] / 4;
    int nthreads = nstates / 4;            // 4 states per thread

    const int TPB = 256;
    int blocks = (nthreads + TPB - 1) / TPB;   // 256 for B=262144
    pendelum2dof_kernel<<<blocks, TPB>>>(y, out);
}

// round 5
// speedup vs baseline: 1.0386x; 1.0386x over previous
#include <cuda_runtime.h>

// Double-pendulum Hamiltonian dynamics, closed form (M1=M2=L1=L2=1, G=9.81).
// State (th1, th2, p1, p2) -> (dq1, dq2, dp1, dp2).
//
// c = cos(th1-th2), s = sin(th1-th2), D = 2 - c^2
// dq1 = (p1 - c p2)/D ; dq2 = (2 p2 - c p1)/D
// N = p1^2 - 2 c p1 p2 + 2 p2^2 ; dK/dc = (c N - D p1 p2)/D^2
// dp1 =  s dK/dc - 2 G sin(th1) ; dp2 = -s dK/dc - G sin(th2)
//
// R5: SM-balanced grid. 296 CTAs (exactly 2 per SM on 148-SM GB300) x 512
// threads (32 warps/SM). Each CTA owns a contiguous chunk of v8-pairs
// (npairs/296 +- 1), one 256-bit load + 2x dyn + one 256-bit store per
// thread. Removes the 512-CTA config's 4-vs-3 CTA/SM imbalance (~15% on
// the critical SM) while RAISING resident warps vs R3.

#define GCONST 9.81f
#define NCTA 296

__device__ __forceinline__ float4 dyn(float th1, float th2, float p1, float p2) {
    float s1, c1, s2, c2;
    __sincosf(th1, &s1, &c1);
    __sincosf(th2, &s2, &c2);

    // sin/cos(th1 - th2) via identities (FMA pipe, saves a MUFU group)
    float c = fmaf(c1, c2, s1 * s2);
    float s = fmaf(s1, c2, -c1 * s2);

    float D    = 2.0f - c * c;
    float invD = __frcp_rn(D);

    float dq1 = (p1 - c * p2) * invD;
    float dq2 = (2.0f * p2 - c * p1) * invD;

    float p1p2 = p1 * p2;
    float N    = p1 * p1 - 2.0f * c * p1p2 + 2.0f * p2 * p2;
    float dKdc = (c * N - D * p1p2) * invD * invD;

    float sd  = s * dKdc;
    float dp1 =  sd - 2.0f * GCONST * s1;
    float dp2 = -sd -        GCONST * s2;

    return make_float4(dq1, dq2, dp1, dp2);
}

__global__ void __launch_bounds__(512)
pendelum2dof_kernel(const float* __restrict__ y,
                    float* __restrict__ out,
                    int per, int rem) {
    // CTA b owns pairs [b*per + min(b,rem), +cnt), cnt = per + (b < rem).
    int b = blockIdx.x;
    int start = b * per + min(b, rem);
    int cnt   = per + (b < rem ? 1 : 0);
    int t = threadIdx.x;
    if (t >= cnt) return;

    size_t p = (size_t)(start + t);
    const float* src = y + p * 8;
    float* dst = out + p * 8;

    float a0, a1, a2, a3, a4, a5, a6, a7;
    asm volatile("ld.global.v8.f32 {%0,%1,%2,%3,%4,%5,%6,%7}, [%8];"
                 : "=f"(a0), "=f"(a1), "=f"(a2), "=f"(a3),
                   "=f"(a4), "=f"(a5), "=f"(a6), "=f"(a7)
                 : "l"(src));

    float4 r0 = dyn(a0, a1, a2, a3);
    float4 r1 = dyn(a4, a5, a6, a7);

    asm volatile("st.global.v8.f32 [%0], {%1,%2,%3,%4,%5,%6,%7,%8};"
                 :
                 : "l"(dst),
                   "f"(r0.x), "f"(r0.y), "f"(r0.z), "f"(r0.w),
                   "f"(r1.x), "f"(r1.y), "f"(r1.z), "f"(r1.w)
                 : "memory");
}

extern "C" void kernel_launch(void* const* d_in, const int* in_sizes, int n_in,
                              void* d_out, int out_size) {
    // d_in[0] = t (unused), d_in[1] = y (B*4 floats)
    const float* y = (const float*)d_in[1];
    float* out = (float*)d_out;
    int npairs = in_sizes[1] / 8;      // one pair = 2 states = 8 floats (B=262144 -> 131072)
    int per = npairs / NCTA;           // 442
    int rem = npairs % NCTA;           // 240
    // per < 512 guaranteed for B = 262144 (442+1 <= 512)

    pendelum2dof_kernel<<<NCTA, 512>>>(y, out, per, rem);
}